// round 12
// baseline (speedup 1.0000x reference)
#include <cuda_runtime.h>
#include <cuda_fp16.h>
#include <cstdint>
#include <cstddef>

// Problem shape (fixed)
#define Bc 16
#define Tc 1024
#define Cc 1024
#define Kc 1024
#define Mc (Bc * Tc)   // 16384
#define NSEG 32
#define SEGL (Tc / NSEG)   // 32
#define LANES (Bc * Cc)    // 16384
#define HL (LANES / 2)     // 8192 half2 lanes

// ---------------------------------------------------------------------------
// Scratch (__device__ globals; no cudaMalloc allowed)
// ---------------------------------------------------------------------------
__device__ __half  g_xh [(size_t)Mc * Kc];    // x as fp16
__device__ __half  g_of [(size_t)Mc * Kc];    // gated wkv output as fp16
__device__ __half  g_k  [(size_t)Mc * Cc];    // k as fp16
__device__ __half  g_r  [(size_t)Mc * Cc];    // r as fp16
__device__ __half  g_wkh[Cc * Kc];            // Wk fp16
__device__ __half  g_wrh[Cc * Kc];            // Wr fp16
__device__ __half  g_woh[Cc * Kc];            // Wo fp16
__device__ float4  g_pc [NSEG * HL];          // per-segment partials (n0,n1,d0,d1)

// ---------------------------------------------------------------------------
// Base-ISA PTX helpers (compile for plain .target sm_103)
// ---------------------------------------------------------------------------
__device__ __forceinline__ uint32_t smem_u32(const void* p) {
    uint32_t a;
    asm("{ .reg .u64 t; cvta.to.shared.u64 t, %1; cvt.u32.u64 %0, t; }"
        : "=r"(a) : "l"(p));
    return a;
}
__device__ __forceinline__ void cp_async16(uint32_t dst, const void* src) {
    asm volatile("cp.async.cg.shared.global [%0], [%1], 16;"
                 :: "r"(dst), "l"(src));
}
__device__ __forceinline__ void cp_commit() {
    asm volatile("cp.async.commit_group;");
}
__device__ __forceinline__ void cp_wait2() {
    asm volatile("cp.async.wait_group 2;" ::: "memory");
}
__device__ __forceinline__ void cp_wait1() {
    asm volatile("cp.async.wait_group 1;" ::: "memory");
}
__device__ __forceinline__ void cp_wait0() {
    asm volatile("cp.async.wait_group 0;" ::: "memory");
}
__device__ __forceinline__ void ldm_x4(uint32_t* r, uint32_t addr) {
    asm volatile("ldmatrix.sync.aligned.m8n8.x4.shared.b16 {%0,%1,%2,%3}, [%4];"
                 : "=r"(r[0]), "=r"(r[1]), "=r"(r[2]), "=r"(r[3]) : "r"(addr));
}
__device__ __forceinline__ void mma_fp16(float* d, const uint32_t* a,
                                         const uint32_t* b) {
    asm volatile(
        "mma.sync.aligned.m16n8k16.row.col.f32.f16.f16.f32 "
        "{%0,%1,%2,%3}, {%4,%5,%6,%7}, {%8,%9}, {%0,%1,%2,%3};"
        : "+f"(d[0]), "+f"(d[1]), "+f"(d[2]), "+f"(d[3])
        : "r"(a[0]), "r"(a[1]), "r"(a[2]), "r"(a[3]), "r"(b[0]), "r"(b[1]));
}

// ---------------------------------------------------------------------------
// Fused fp32 -> fp16 convert: x (nx4 float4s) then Wk, Wr, Wo (nw4 each)
// ---------------------------------------------------------------------------
#define NX4 ((Mc * Kc) / 4)       // 4194304
#define NW4 ((Cc * Kc) / 4)       // 262144
#define NCVT (NX4 + 3 * NW4)      // 4980736 (= 19456 * 256)

__global__ void cvt_all(const float* __restrict__ x,
                        const float* __restrict__ Wk,
                        const float* __restrict__ Wr,
                        const float* __restrict__ Wo,
                        __half* __restrict__ xh,
                        __half* __restrict__ wkh,
                        __half* __restrict__ wrh,
                        __half* __restrict__ woh)
{
    int i = blockIdx.x * blockDim.x + threadIdx.x;
    if (i >= NCVT) return;
    const float* src;
    __half* dst;
    int j = i;
    if (j < NX4)              { src = x;  dst = xh;  }
    else if ((j -= NX4) < NW4){ src = Wk; dst = wkh; }
    else if ((j -= NW4) < NW4){ src = Wr; dst = wrh; }
    else                      { j -= NW4; src = Wo; dst = woh; }
    float4 v = reinterpret_cast<const float4*>(src)[j];
    reinterpret_cast<__half2*>(dst)[2 * j]     = __floats2half2_rn(v.x, v.y);
    reinterpret_cast<__half2*>(dst)[2 * j + 1] = __floats2half2_rn(v.z, v.w);
}

// ---------------------------------------------------------------------------
// HMMA fp16 NT GEMM (R8 structure — measured best): C = A * B^T.
// CTA tile 128(M) x 256(N), K-chunk 64 (128B swizzled rows), 8 warps in a
// 2(m) x 4(n) grid -> warp tile 64x64. 4-stage cp.async pipeline, issue
// after compute, two __syncthreads per chunk.
// ---------------------------------------------------------------------------
#define BK 64
#define B_OFF   16384               // A tile 128*128B
#define STAGE_B 49152               // A(16KB) + B(32KB)
#define NSTAGE  4
#define GEMM_SMEM (NSTAGE * STAGE_B)   // 196608
#define NCHUNK (Kc / BK)            // 16

__global__ __launch_bounds__(256, 1)
void gemm_hmma(const __half* __restrict__ A,
               const __half* __restrict__ B0,
               void* __restrict__ C0,
               const __half* __restrict__ B1,
               void* __restrict__ C1,
               int half_out)
{
    extern __shared__ char smem_raw[];
    const uint32_t sbase = smem_u32(smem_raw);

    const int tid  = threadIdx.x;
    const int wid  = tid >> 5;
    const int lane = tid & 31;

    const __half* B = blockIdx.z ? B1 : B0;
    void* Cmat      = blockIdx.z ? C1 : C0;

    const int m0 = blockIdx.y * 128;
    const int n0 = blockIdx.x * 256;

    const __half* Ap = A + (size_t)m0 * Kc;
    const __half* Bp = B + (size_t)n0 * Kc;

    // ---- cp.async segment maps ---------------------------------------------
    uint32_t sdstA[4], goffA[4];
#pragma unroll
    for (int i = 0; i < 4; i++) {
        const int sid = i * 256 + tid;        // 0..1023
        const int row = sid >> 3;             // 0..127
        const int s   = sid & 7;
        sdstA[i] = row * 128 + ((s ^ (row & 7)) << 4);
        goffA[i] = row * Kc + s * 8;
    }
    uint32_t sdstB[8], goffB[8];
#pragma unroll
    for (int j = 0; j < 8; j++) {
        const int sid = j * 256 + tid;        // 0..2047
        const int row = sid >> 3;             // 0..255
        const int s   = sid & 7;
        sdstB[j] = B_OFF + row * 128 + ((s ^ (row & 7)) << 4);
        goffB[j] = row * Kc + s * 8;
    }

    // ---- warp tiling -------------------------------------------------------
    const int wm = (wid & 1) * 64;
    const int wn = (wid >> 1) * 64;

    float acc[4][8][4];
#pragma unroll
    for (int mi = 0; mi < 4; mi++)
#pragma unroll
        for (int ni = 0; ni < 8; ni++)
#pragma unroll
            for (int j = 0; j < 4; j++) acc[mi][ni][j] = 0.f;

    const int a_row = wm + (lane & 15);
    const int a_ks  = lane >> 4;
    const int b_row = wn + (lane & 7) + ((lane >> 4) << 3);
    const int b_ks  = (lane >> 3) & 1;

#define ISSUE_CHUNK(chunk) do {                                                \
    const uint32_t _buf = sbase + ((chunk) & (NSTAGE - 1)) * STAGE_B;          \
    const int _ko = (chunk) * BK;                                              \
    _Pragma("unroll")                                                          \
    for (int i = 0; i < 4; i++)                                                \
        cp_async16(_buf + sdstA[i], Ap + goffA[i] + _ko);                      \
    _Pragma("unroll")                                                          \
    for (int j = 0; j < 8; j++)                                                \
        cp_async16(_buf + sdstB[j], Bp + goffB[j] + _ko);                      \
    cp_commit();                                                               \
} while (0)

    ISSUE_CHUNK(0);
    ISSUE_CHUNK(1);
    ISSUE_CHUNK(2);

    for (int c = 0; c < NCHUNK; ++c) {
        if (c <= NCHUNK - 3)      cp_wait2();
        else if (c == NCHUNK - 2) cp_wait1();
        else                      cp_wait0();
        __syncthreads();

        const uint32_t buf = sbase + (c & (NSTAGE - 1)) * STAGE_B;
#pragma unroll
        for (int ks = 0; ks < 4; ks++) {
            uint32_t af[4][4];
#pragma unroll
            for (int mi = 0; mi < 4; mi++) {
                const int row = a_row + mi * 16;
                const int sg  = (ks * 2 + a_ks) ^ (row & 7);
                ldm_x4(af[mi], buf + row * 128 + (sg << 4));
            }
#pragma unroll
            for (int ni = 0; ni < 4; ni++) {
                const int row = b_row + ni * 16;
                const int sg  = (ks * 2 + b_ks) ^ (row & 7);
                uint32_t bh[4];
                ldm_x4(bh, buf + B_OFF + row * 128 + (sg << 4));
#pragma unroll
                for (int mi = 0; mi < 4; mi++) {
                    mma_fp16(acc[mi][2 * ni],     af[mi], bh);
                    mma_fp16(acc[mi][2 * ni + 1], af[mi], bh + 2);
                }
            }
        }
        __syncthreads();
        if (c + 3 < NCHUNK) {
            ISSUE_CHUNK(c + 3);
        }
    }
#undef ISSUE_CHUNK

    // ---- epilogue ----------------------------------------------------------
    const int er = lane >> 2;
    const int ec = (lane & 3) * 2;
    if (half_out) {
        __half* C = (__half*)Cmat;
#pragma unroll
        for (int mi = 0; mi < 4; mi++) {
            const int mb = m0 + wm + mi * 16;
#pragma unroll
            for (int ni = 0; ni < 8; ni++) {
                const int nb = n0 + wn + ni * 8;
                *reinterpret_cast<__half2*>(C + (size_t)(mb + er) * Cc + nb + ec) =
                    __floats2half2_rn(acc[mi][ni][0], acc[mi][ni][1]);
                *reinterpret_cast<__half2*>(C + (size_t)(mb + 8 + er) * Cc + nb + ec) =
                    __floats2half2_rn(acc[mi][ni][2], acc[mi][ni][3]);
            }
        }
    } else {
        float* C = (float*)Cmat;
#pragma unroll
        for (int mi = 0; mi < 4; mi++) {
            const int mb = m0 + wm + mi * 16;
#pragma unroll
            for (int ni = 0; ni < 8; ni++) {
                const int nb = n0 + wn + ni * 8;
                float2 v0 = make_float2(acc[mi][ni][0], acc[mi][ni][1]);
                float2 v1 = make_float2(acc[mi][ni][2], acc[mi][ni][3]);
                *reinterpret_cast<float2*>(C + (size_t)(mb + er) * Cc + nb + ec) = v0;
                *reinterpret_cast<float2*>(C + (size_t)(mb + 8 + er) * Cc + nb + ec) = v1;
            }
        }
    }
}

// ---------------------------------------------------------------------------
// WKV pass 1 (half2): per-segment partial (num, den) for 2 channels/thread.
//   local = sum_i ew^(L-1-i) * e^{k_i} * [v_i, 1]
// idx = seg*HL + bc2; writes one float4 (n0, n1, d0, d1).
// ---------------------------------------------------------------------------
__global__ void wkv_pass1(const __half2* __restrict__ kbuf,
                          const __half2* __restrict__ rbuf,
                          const float* __restrict__ td,
                          float4* __restrict__ pc)
{
    const int idx = blockIdx.x * blockDim.x + threadIdx.x;
    if (idx >= NSEG * HL) return;
    const int c2  = idx & (Cc / 2 - 1);
    const int b   = (idx >> 9) & (Bc - 1);
    const int seg = idx >> 13;

    const float ew0 = __expf(-__expf(td[2 * c2]));
    const float ew1 = __expf(-__expf(td[2 * c2 + 1]));

    const size_t base = ((size_t)b * Tc + (size_t)seg * SEGL) * (Cc / 2) + c2;
    const __half2* kp = kbuf + base;
    const __half2* rp = rbuf + base;

    float n0 = 0.f, d0 = 0.f, n1 = 0.f, d1 = 0.f;
    for (int t = 0; t < SEGL; t += 8) {
        float2 kt[8], rt[8];
#pragma unroll
        for (int j = 0; j < 8; j++) {                 // MLP = 16
            kt[j] = __half22float2(kp[(size_t)(t + j) * (Cc / 2)]);
            rt[j] = __half22float2(rp[(size_t)(t + j) * (Cc / 2)]);
        }
#pragma unroll
        for (int j = 0; j < 8; j++) {
            const float e0 = __expf(kt[j].x);
            const float e1 = __expf(kt[j].y);
            n0 = fmaf(ew0, n0, e0 * rt[j].x);
            d0 = fmaf(ew0, d0, e0);
            n1 = fmaf(ew1, n1, e1 * rt[j].y);
            d1 = fmaf(ew1, d1, e1);
        }
    }
    pc[idx] = make_float4(n0, n1, d0, d1);
}

// ---------------------------------------------------------------------------
// WKV pass 2: block = (32 segments x 8 half2-lanes). Partials loaded into
// SMEM once; each thread prefix-combines its carry from SMEM, then rescans
// its segment, emitting o = sigmoid(r) * y as fp16. Eliminates the ~64MB of
// redundant carry DRAM traffic of the per-thread global prefix loop.
// ---------------------------------------------------------------------------
__global__ __launch_bounds__(256)
void wkv_pass2(const __half2* __restrict__ kbuf,
               const __half2* __restrict__ rbuf,
               const float* __restrict__ td,
               const float* __restrict__ tf,
               const float4* __restrict__ pc,
               __half2* __restrict__ obuf)
{
    __shared__ float4 sp[NSEG][8];

    const int tid = threadIdx.x;
    const int seg = tid >> 3;                 // 0..31
    const int l2  = tid & 7;                  // 0..7
    const int bc2 = blockIdx.x * 8 + l2;      // global half2 lane
    const int c2  = bc2 & (Cc / 2 - 1);
    const int b   = bc2 >> 9;

    // cooperative load of this lane-group's partials (all segments)
    sp[seg][l2] = pc[seg * HL + bc2];
    __syncthreads();

    const float etd0 = __expf(td[2 * c2]);
    const float etd1 = __expf(td[2 * c2 + 1]);
    const float ew0  = __expf(-etd0);
    const float ew1  = __expf(-etd1);
    const float ewL0 = __expf(-etd0 * (float)SEGL);
    const float ewL1 = __expf(-etd1 * (float)SEGL);
    const float eu0  = __expf(tf[2 * c2]);
    const float eu1  = __expf(tf[2 * c2 + 1]);

    // carry = combine of segments 0..seg-1 (same order as R10 -> same bits)
    float n0 = 0.f, d0 = 0.f, n1 = 0.f, d1 = 0.f;
    for (int s = 0; s < seg; s++) {
        const float4 p = sp[s][l2];
        n0 = fmaf(ewL0, n0, p.x);
        n1 = fmaf(ewL1, n1, p.y);
        d0 = fmaf(ewL0, d0, p.z);
        d1 = fmaf(ewL1, d1, p.w);
    }

    const size_t base = ((size_t)b * Tc + (size_t)seg * SEGL) * (Cc / 2) + c2;
    const __half2* kp = kbuf + base;
    const __half2* rp = rbuf + base;
    __half2*       op = obuf + base;

    for (int t = 0; t < SEGL; t += 8) {
        float2 kt[8], rt[8];
#pragma unroll
        for (int j = 0; j < 8; j++) {
            kt[j] = __half22float2(kp[(size_t)(t + j) * (Cc / 2)]);
            rt[j] = __half22float2(rp[(size_t)(t + j) * (Cc / 2)]);
        }
#pragma unroll
        for (int j = 0; j < 8; j++) {
            const float e0  = __expf(kt[j].x);
            const float e1  = __expf(kt[j].y);
            const float eu_k0 = eu0 * e0;
            const float eu_k1 = eu1 * e1;
            const float y0  = __fdividef(fmaf(eu_k0, rt[j].x, n0), d0 + eu_k0);
            const float y1  = __fdividef(fmaf(eu_k1, rt[j].y, n1), d1 + eu_k1);
            n0 = fmaf(ew0, n0, e0 * rt[j].x);
            d0 = fmaf(ew0, d0, e0);
            n1 = fmaf(ew1, n1, e1 * rt[j].y);
            d1 = fmaf(ew1, d1, e1);
            const float s0 = __fdividef(1.f, 1.f + __expf(-rt[j].x));
            const float s1 = __fdividef(1.f, 1.f + __expf(-rt[j].y));
            op[(size_t)(t + j) * (Cc / 2)] = __floats2half2_rn(s0 * y0, s1 * y1);
        }
    }
}

// ---------------------------------------------------------------------------
// Launch sequence (graph-capturable; default stream)
// ---------------------------------------------------------------------------
extern "C" void kernel_launch(void* const* d_in, const int* in_sizes, int n_in,
                              void* d_out, int out_size)
{
    const float* x  = (const float*)d_in[0];
    const float* Wk = (const float*)d_in[1];
    const float* Wr = (const float*)d_in[2];
    const float* Wo = (const float*)d_in[3];
    const float* td = (const float*)d_in[4];
    const float* tf = (const float*)d_in[5];
    float* out = (float*)d_out;

    __half *xh, *of, *wkh, *wrh, *woh, *pk, *pr;
    float4* pc;
    cudaGetSymbolAddress((void**)&xh,  g_xh);
    cudaGetSymbolAddress((void**)&of,  g_of);
    cudaGetSymbolAddress((void**)&pk,  g_k);
    cudaGetSymbolAddress((void**)&pr,  g_r);
    cudaGetSymbolAddress((void**)&wkh, g_wkh);
    cudaGetSymbolAddress((void**)&wrh, g_wrh);
    cudaGetSymbolAddress((void**)&woh, g_woh);
    cudaGetSymbolAddress((void**)&pc,  g_pc);

    cudaFuncSetAttribute(gemm_hmma, cudaFuncAttributeMaxDynamicSharedMemorySize,
                         GEMM_SMEM);

    // fused fp32 -> fp16 conversions (x + all three weights)
    cvt_all<<<NCVT / 256, 256>>>(x, Wk, Wr, Wo, xh, wkh, wrh, woh);

    // z=0: k = x*Wk^T ; z=1: r = x*Wr^T ; both -> fp16
    dim3 grid_kr(Cc / 256, Mc / 128, 2);
    gemm_hmma<<<grid_kr, 256, GEMM_SMEM>>>(xh, wkh, pk, wrh, pr, 1);

    // segment-parallel wkv
    wkv_pass1<<<(NSEG * HL) / 256, 256>>>((const __half2*)pk,
                                          (const __half2*)pr, td, pc);
    wkv_pass2<<<HL / 8, 256>>>((const __half2*)pk, (const __half2*)pr, td, tf,
                               pc, (__half2*)of);

    // out = o * Wo^T, fp32 output
    dim3 grid_o(Cc / 256, Mc / 128, 1);
    gemm_hmma<<<grid_o, 256, GEMM_SMEM>>>(of, woh, out, woh, out, 0);
}

// round 13
// speedup vs baseline: 1.0020x; 1.0020x over previous
#include <cuda_runtime.h>
#include <cuda_fp16.h>
#include <cstdint>
#include <cstddef>

// Problem shape (fixed)
#define Bc 16
#define Tc 1024
#define Cc 1024
#define Kc 1024
#define Mc (Bc * Tc)   // 16384
#define NSEG 32
#define SEGL (Tc / NSEG)   // 32
#define LANES (Bc * Cc)    // 16384
#define HL (LANES / 2)     // 8192 half2 lanes

// ---------------------------------------------------------------------------
// Scratch (__device__ globals; no cudaMalloc allowed)
// ---------------------------------------------------------------------------
__device__ __half  g_xh [(size_t)Mc * Kc];    // x as fp16
__device__ __half  g_of [(size_t)Mc * Kc];    // gated wkv output as fp16
__device__ __half  g_k  [(size_t)Mc * Cc];    // k as fp16
__device__ __half  g_r  [(size_t)Mc * Cc];    // r as fp16
__device__ __half  g_wkh[Cc * Kc];            // Wk fp16
__device__ __half  g_wrh[Cc * Kc];            // Wr fp16
__device__ __half  g_woh[Cc * Kc];            // Wo fp16
__device__ float4  g_pc [NSEG * HL];          // per-segment partials (n0,n1,d0,d1)

// ---------------------------------------------------------------------------
// Base-ISA PTX helpers (compile for plain .target sm_103)
// ---------------------------------------------------------------------------
__device__ __forceinline__ uint32_t smem_u32(const void* p) {
    uint32_t a;
    asm("{ .reg .u64 t; cvta.to.shared.u64 t, %1; cvt.u32.u64 %0, t; }"
        : "=r"(a) : "l"(p));
    return a;
}
__device__ __forceinline__ void cp_async16(uint32_t dst, const void* src) {
    asm volatile("cp.async.cg.shared.global [%0], [%1], 16;"
                 :: "r"(dst), "l"(src));
}
__device__ __forceinline__ void cp_commit() {
    asm volatile("cp.async.commit_group;");
}
__device__ __forceinline__ void cp_wait2() {
    asm volatile("cp.async.wait_group 2;" ::: "memory");
}
__device__ __forceinline__ void cp_wait1() {
    asm volatile("cp.async.wait_group 1;" ::: "memory");
}
__device__ __forceinline__ void cp_wait0() {
    asm volatile("cp.async.wait_group 0;" ::: "memory");
}
__device__ __forceinline__ void ldm_x4(uint32_t* r, uint32_t addr) {
    asm volatile("ldmatrix.sync.aligned.m8n8.x4.shared.b16 {%0,%1,%2,%3}, [%4];"
                 : "=r"(r[0]), "=r"(r[1]), "=r"(r[2]), "=r"(r[3]) : "r"(addr));
}
__device__ __forceinline__ void mma_fp16(float* d, const uint32_t* a,
                                         const uint32_t* b) {
    asm volatile(
        "mma.sync.aligned.m16n8k16.row.col.f32.f16.f16.f32 "
        "{%0,%1,%2,%3}, {%4,%5,%6,%7}, {%8,%9}, {%0,%1,%2,%3};"
        : "+f"(d[0]), "+f"(d[1]), "+f"(d[2]), "+f"(d[3])
        : "r"(a[0]), "r"(a[1]), "r"(a[2]), "r"(a[3]), "r"(b[0]), "r"(b[1]));
}

// ---------------------------------------------------------------------------
// Fused fp32 -> fp16 convert: x then Wk, Wr, Wo
// ---------------------------------------------------------------------------
#define NX4 ((Mc * Kc) / 4)       // 4194304
#define NW4 ((Cc * Kc) / 4)       // 262144
#define NCVT (NX4 + 3 * NW4)      // 4980736 (= 19456 * 256)

__global__ void cvt_all(const float* __restrict__ x,
                        const float* __restrict__ Wk,
                        const float* __restrict__ Wr,
                        const float* __restrict__ Wo,
                        __half* __restrict__ xh,
                        __half* __restrict__ wkh,
                        __half* __restrict__ wrh,
                        __half* __restrict__ woh)
{
    int i = blockIdx.x * blockDim.x + threadIdx.x;
    if (i >= NCVT) return;
    const float* src;
    __half* dst;
    int j = i;
    if (j < NX4)              { src = x;  dst = xh;  }
    else if ((j -= NX4) < NW4){ src = Wk; dst = wkh; }
    else if ((j -= NW4) < NW4){ src = Wr; dst = wrh; }
    else                      { j -= NW4; src = Wo; dst = woh; }
    float4 v = reinterpret_cast<const float4*>(src)[j];
    reinterpret_cast<__half2*>(dst)[2 * j]     = __floats2half2_rn(v.x, v.y);
    reinterpret_cast<__half2*>(dst)[2 * j + 1] = __floats2half2_rn(v.z, v.w);
}

// ---------------------------------------------------------------------------
// HMMA fp16 NT GEMM (R8 structure — measured best): C = A * B^T.
// CTA tile 128(M) x 256(N), K-chunk 64 (128B swizzled rows), 8 warps in a
// 2(m) x 4(n) grid -> warp tile 64x64. 4-stage cp.async pipeline, issue
// after compute, two __syncthreads per chunk.
// ---------------------------------------------------------------------------
#define BK 64
#define B_OFF   16384               // A tile 128*128B
#define STAGE_B 49152               // A(16KB) + B(32KB)
#define NSTAGE  4
#define GEMM_SMEM (NSTAGE * STAGE_B)   // 196608
#define NCHUNK (Kc / BK)            // 16

__global__ __launch_bounds__(256, 1)
void gemm_hmma(const __half* __restrict__ A,
               const __half* __restrict__ B0,
               void* __restrict__ C0,
               const __half* __restrict__ B1,
               void* __restrict__ C1,
               int half_out)
{
    extern __shared__ char smem_raw[];
    const uint32_t sbase = smem_u32(smem_raw);

    const int tid  = threadIdx.x;
    const int wid  = tid >> 5;
    const int lane = tid & 31;

    const __half* B = blockIdx.z ? B1 : B0;
    void* Cmat      = blockIdx.z ? C1 : C0;

    const int m0 = blockIdx.y * 128;
    const int n0 = blockIdx.x * 256;

    const __half* Ap = A + (size_t)m0 * Kc;
    const __half* Bp = B + (size_t)n0 * Kc;

    // ---- cp.async segment maps ---------------------------------------------
    uint32_t sdstA[4], goffA[4];
#pragma unroll
    for (int i = 0; i < 4; i++) {
        const int sid = i * 256 + tid;        // 0..1023
        const int row = sid >> 3;             // 0..127
        const int s   = sid & 7;
        sdstA[i] = row * 128 + ((s ^ (row & 7)) << 4);
        goffA[i] = row * Kc + s * 8;
    }
    uint32_t sdstB[8], goffB[8];
#pragma unroll
    for (int j = 0; j < 8; j++) {
        const int sid = j * 256 + tid;        // 0..2047
        const int row = sid >> 3;             // 0..255
        const int s   = sid & 7;
        sdstB[j] = B_OFF + row * 128 + ((s ^ (row & 7)) << 4);
        goffB[j] = row * Kc + s * 8;
    }

    // ---- warp tiling -------------------------------------------------------
    const int wm = (wid & 1) * 64;
    const int wn = (wid >> 1) * 64;

    float acc[4][8][4];
#pragma unroll
    for (int mi = 0; mi < 4; mi++)
#pragma unroll
        for (int ni = 0; ni < 8; ni++)
#pragma unroll
            for (int j = 0; j < 4; j++) acc[mi][ni][j] = 0.f;

    const int a_row = wm + (lane & 15);
    const int a_ks  = lane >> 4;
    const int b_row = wn + (lane & 7) + ((lane >> 4) << 3);
    const int b_ks  = (lane >> 3) & 1;

#define ISSUE_CHUNK(chunk) do {                                                \
    const uint32_t _buf = sbase + ((chunk) & (NSTAGE - 1)) * STAGE_B;          \
    const int _ko = (chunk) * BK;                                              \
    _Pragma("unroll")                                                          \
    for (int i = 0; i < 4; i++)                                                \
        cp_async16(_buf + sdstA[i], Ap + goffA[i] + _ko);                      \
    _Pragma("unroll")                                                          \
    for (int j = 0; j < 8; j++)                                                \
        cp_async16(_buf + sdstB[j], Bp + goffB[j] + _ko);                      \
    cp_commit();                                                               \
} while (0)

    ISSUE_CHUNK(0);
    ISSUE_CHUNK(1);
    ISSUE_CHUNK(2);

    for (int c = 0; c < NCHUNK; ++c) {
        if (c <= NCHUNK - 3)      cp_wait2();
        else if (c == NCHUNK - 2) cp_wait1();
        else                      cp_wait0();
        __syncthreads();

        const uint32_t buf = sbase + (c & (NSTAGE - 1)) * STAGE_B;
#pragma unroll
        for (int ks = 0; ks < 4; ks++) {
            uint32_t af[4][4];
#pragma unroll
            for (int mi = 0; mi < 4; mi++) {
                const int row = a_row + mi * 16;
                const int sg  = (ks * 2 + a_ks) ^ (row & 7);
                ldm_x4(af[mi], buf + row * 128 + (sg << 4));
            }
#pragma unroll
            for (int ni = 0; ni < 4; ni++) {
                const int row = b_row + ni * 16;
                const int sg  = (ks * 2 + b_ks) ^ (row & 7);
                uint32_t bh[4];
                ldm_x4(bh, buf + B_OFF + row * 128 + (sg << 4));
#pragma unroll
                for (int mi = 0; mi < 4; mi++) {
                    mma_fp16(acc[mi][2 * ni],     af[mi], bh);
                    mma_fp16(acc[mi][2 * ni + 1], af[mi], bh + 2);
                }
            }
        }
        __syncthreads();
        if (c + 3 < NCHUNK) {
            ISSUE_CHUNK(c + 3);
        }
    }
#undef ISSUE_CHUNK

    // ---- epilogue ----------------------------------------------------------
    const int er = lane >> 2;
    const int ec = (lane & 3) * 2;
    if (half_out) {
        __half* C = (__half*)Cmat;
#pragma unroll
        for (int mi = 0; mi < 4; mi++) {
            const int mb = m0 + wm + mi * 16;
#pragma unroll
            for (int ni = 0; ni < 8; ni++) {
                const int nb = n0 + wn + ni * 8;
                *reinterpret_cast<__half2*>(C + (size_t)(mb + er) * Cc + nb + ec) =
                    __floats2half2_rn(acc[mi][ni][0], acc[mi][ni][1]);
                *reinterpret_cast<__half2*>(C + (size_t)(mb + 8 + er) * Cc + nb + ec) =
                    __floats2half2_rn(acc[mi][ni][2], acc[mi][ni][3]);
            }
        }
    } else {
        float* C = (float*)Cmat;
#pragma unroll
        for (int mi = 0; mi < 4; mi++) {
            const int mb = m0 + wm + mi * 16;
#pragma unroll
            for (int ni = 0; ni < 8; ni++) {
                const int nb = n0 + wn + ni * 8;
                float2 v0 = make_float2(acc[mi][ni][0], acc[mi][ni][1]);
                float2 v1 = make_float2(acc[mi][ni][2], acc[mi][ni][3]);
                *reinterpret_cast<float2*>(C + (size_t)(mb + er) * Cc + nb + ec) = v0;
                *reinterpret_cast<float2*>(C + (size_t)(mb + 8 + er) * Cc + nb + ec) = v1;
            }
        }
    }
}

// ---------------------------------------------------------------------------
// WKV pass 1 (half2): per-segment partial (num, den) for 2 channels/thread.
//   local = sum_i ew^(L-1-i) * e^{k_i} * [v_i, 1]
// idx = seg*HL + bc2; writes one float4 (n0, n1, d0, d1).
// ---------------------------------------------------------------------------
__global__ void wkv_pass1(const __half2* __restrict__ kbuf,
                          const __half2* __restrict__ rbuf,
                          const float* __restrict__ td,
                          float4* __restrict__ pc)
{
    const int idx = blockIdx.x * blockDim.x + threadIdx.x;
    if (idx >= NSEG * HL) return;
    const int c2  = idx & (Cc / 2 - 1);
    const int b   = (idx >> 9) & (Bc - 1);
    const int seg = idx >> 13;

    const float ew0 = __expf(-__expf(td[2 * c2]));
    const float ew1 = __expf(-__expf(td[2 * c2 + 1]));

    const size_t base = ((size_t)b * Tc + (size_t)seg * SEGL) * (Cc / 2) + c2;
    const __half2* kp = kbuf + base;
    const __half2* rp = rbuf + base;

    float n0 = 0.f, d0 = 0.f, n1 = 0.f, d1 = 0.f;
    for (int t = 0; t < SEGL; t += 8) {
        float2 kt[8], rt[8];
#pragma unroll
        for (int j = 0; j < 8; j++) {                 // MLP = 16
            kt[j] = __half22float2(kp[(size_t)(t + j) * (Cc / 2)]);
            rt[j] = __half22float2(rp[(size_t)(t + j) * (Cc / 2)]);
        }
#pragma unroll
        for (int j = 0; j < 8; j++) {
            const float e0 = __expf(kt[j].x);
            const float e1 = __expf(kt[j].y);
            n0 = fmaf(ew0, n0, e0 * rt[j].x);
            d0 = fmaf(ew0, d0, e0);
            n1 = fmaf(ew1, n1, e1 * rt[j].y);
            d1 = fmaf(ew1, d1, e1);
        }
    }
    pc[idx] = make_float4(n0, n1, d0, d1);
}

// ---------------------------------------------------------------------------
// WKV pass 2 (R10 coalesced mapping): prefix-combine carries from gmem
// (float4, warp-coalesced), rescan segment. Output fused as
//   o = (euk*r + num) * rcp((den + euk) * (1 + e^-r))
// -> 3 MUFU ops per element (was 4).
// ---------------------------------------------------------------------------
__global__ void wkv_pass2(const __half2* __restrict__ kbuf,
                          const __half2* __restrict__ rbuf,
                          const float* __restrict__ td,
                          const float* __restrict__ tf,
                          const float4* __restrict__ pc,
                          __half2* __restrict__ obuf)
{
    const int idx = blockIdx.x * blockDim.x + threadIdx.x;
    if (idx >= NSEG * HL) return;
    const int c2  = idx & (Cc / 2 - 1);
    const int b   = (idx >> 9) & (Bc - 1);
    const int bc2 = idx & (HL - 1);
    const int seg = idx >> 13;

    const float etd0 = __expf(td[2 * c2]);
    const float etd1 = __expf(td[2 * c2 + 1]);
    const float ew0  = __expf(-etd0);
    const float ew1  = __expf(-etd1);
    const float ewL0 = __expf(-etd0 * (float)SEGL);
    const float ewL1 = __expf(-etd1 * (float)SEGL);
    const float eu0  = __expf(tf[2 * c2]);
    const float eu1  = __expf(tf[2 * c2 + 1]);

    // carry = combine of segments 0..seg-1 (coalesced 16B float4 loads)
    float n0 = 0.f, d0 = 0.f, n1 = 0.f, d1 = 0.f;
    for (int s = 0; s < seg; s++) {
        const float4 p = pc[s * HL + bc2];
        n0 = fmaf(ewL0, n0, p.x);
        n1 = fmaf(ewL1, n1, p.y);
        d0 = fmaf(ewL0, d0, p.z);
        d1 = fmaf(ewL1, d1, p.w);
    }

    const size_t base = ((size_t)b * Tc + (size_t)seg * SEGL) * (Cc / 2) + c2;
    const __half2* kp = kbuf + base;
    const __half2* rp = rbuf + base;
    __half2*       op = obuf + base;

    for (int t = 0; t < SEGL; t += 8) {
        float2 kt[8], rt[8];
#pragma unroll
        for (int j = 0; j < 8; j++) {
            kt[j] = __half22float2(kp[(size_t)(t + j) * (Cc / 2)]);
            rt[j] = __half22float2(rp[(size_t)(t + j) * (Cc / 2)]);
        }
#pragma unroll
        for (int j = 0; j < 8; j++) {
            const float e0  = __expf(kt[j].x);              // MUFU 1
            const float e1  = __expf(kt[j].y);
            const float em0 = __expf(-rt[j].x);             // MUFU 2
            const float em1 = __expf(-rt[j].y);
            const float eu_k0 = eu0 * e0;
            const float eu_k1 = eu1 * e1;
            const float num0 = fmaf(eu_k0, rt[j].x, n0);
            const float num1 = fmaf(eu_k1, rt[j].y, n1);
            const float den0 = (d0 + eu_k0) * (1.f + em0);
            const float den1 = (d1 + eu_k1) * (1.f + em1);
            const float o0 = num0 * __frcp_rn(den0) ;       // MUFU 3 (rcp)
            const float o1 = num1 * __frcp_rn(den1);
            n0 = fmaf(ew0, n0, e0 * rt[j].x);
            d0 = fmaf(ew0, d0, e0);
            n1 = fmaf(ew1, n1, e1 * rt[j].y);
            d1 = fmaf(ew1, d1, e1);
            op[(size_t)(t + j) * (Cc / 2)] = __floats2half2_rn(o0, o1);
        }
    }
}

// ---------------------------------------------------------------------------
// Launch sequence (graph-capturable; default stream)
// ---------------------------------------------------------------------------
extern "C" void kernel_launch(void* const* d_in, const int* in_sizes, int n_in,
                              void* d_out, int out_size)
{
    const float* x  = (const float*)d_in[0];
    const float* Wk = (const float*)d_in[1];
    const float* Wr = (const float*)d_in[2];
    const float* Wo = (const float*)d_in[3];
    const float* td = (const float*)d_in[4];
    const float* tf = (const float*)d_in[5];
    float* out = (float*)d_out;

    __half *xh, *of, *wkh, *wrh, *woh, *pk, *pr;
    float4* pc;
    cudaGetSymbolAddress((void**)&xh,  g_xh);
    cudaGetSymbolAddress((void**)&of,  g_of);
    cudaGetSymbolAddress((void**)&pk,  g_k);
    cudaGetSymbolAddress((void**)&pr,  g_r);
    cudaGetSymbolAddress((void**)&wkh, g_wkh);
    cudaGetSymbolAddress((void**)&wrh, g_wrh);
    cudaGetSymbolAddress((void**)&woh, g_woh);
    cudaGetSymbolAddress((void**)&pc,  g_pc);

    cudaFuncSetAttribute(gemm_hmma, cudaFuncAttributeMaxDynamicSharedMemorySize,
                         GEMM_SMEM);

    // fused fp32 -> fp16 conversions (x + all three weights)
    cvt_all<<<NCVT / 256, 256>>>(x, Wk, Wr, Wo, xh, wkh, wrh, woh);

    // z=0: k = x*Wk^T ; z=1: r = x*Wr^T ; both -> fp16
    dim3 grid_kr(Cc / 256, Mc / 128, 2);
    gemm_hmma<<<grid_kr, 256, GEMM_SMEM>>>(xh, wkh, pk, wrh, pr, 1);

    // segment-parallel wkv
    wkv_pass1<<<(NSEG * HL) / 256, 256>>>((const __half2*)pk,
                                          (const __half2*)pr, td, pc);
    wkv_pass2<<<(NSEG * HL) / 256, 256>>>((const __half2*)pk,
                                          (const __half2*)pr, td, tf, pc,
                                          (__half2*)of);

    // out = o * Wo^T, fp32 output
    dim3 grid_o(Cc / 256, Mc / 128, 1);
    gemm_hmma<<<grid_o, 256, GEMM_SMEM>>>(of, woh, out, woh, out, 0);
}

// round 14
// speedup vs baseline: 1.0075x; 1.0055x over previous
#include <cuda_runtime.h>
#include <cuda_fp16.h>
#include <cstdint>
#include <cstddef>

// Problem shape (fixed)
#define Bc 16
#define Tc 1024
#define Cc 1024
#define Kc 1024
#define Mc (Bc * Tc)   // 16384
#define NSEG 32
#define SEGL (Tc / NSEG)   // 32
#define LANES (Bc * Cc)    // 16384
#define HL (LANES / 2)     // 8192 half2 lanes

// ---------------------------------------------------------------------------
// Scratch (__device__ globals; no cudaMalloc allowed)
// ---------------------------------------------------------------------------
__device__ __half  g_xh [(size_t)Mc * Kc];    // x as fp16
__device__ __half  g_of [(size_t)Mc * Kc];    // gated wkv output as fp16
__device__ __half  g_k  [(size_t)Mc * Cc];    // k as fp16
__device__ __half  g_r  [(size_t)Mc * Cc];    // r as fp16
__device__ __half  g_wkh[Cc * Kc];            // Wk fp16
__device__ __half  g_wrh[Cc * Kc];            // Wr fp16
__device__ __half  g_woh[Cc * Kc];            // Wo fp16
__device__ float4  g_pc [NSEG * HL];          // per-segment partials (n0,n1,d0,d1)

// ---------------------------------------------------------------------------
// Base-ISA PTX helpers (compile for plain .target sm_103)
// ---------------------------------------------------------------------------
__device__ __forceinline__ uint32_t smem_u32(const void* p) {
    uint32_t a;
    asm("{ .reg .u64 t; cvta.to.shared.u64 t, %1; cvt.u32.u64 %0, t; }"
        : "=r"(a) : "l"(p));
    return a;
}
__device__ __forceinline__ void cp_async16(uint32_t dst, const void* src) {
    asm volatile("cp.async.cg.shared.global [%0], [%1], 16;"
                 :: "r"(dst), "l"(src));
}
__device__ __forceinline__ void cp_commit() {
    asm volatile("cp.async.commit_group;");
}
__device__ __forceinline__ void cp_wait2() {
    asm volatile("cp.async.wait_group 2;" ::: "memory");
}
__device__ __forceinline__ void cp_wait1() {
    asm volatile("cp.async.wait_group 1;" ::: "memory");
}
__device__ __forceinline__ void cp_wait0() {
    asm volatile("cp.async.wait_group 0;" ::: "memory");
}
__device__ __forceinline__ void ldm_x4(uint32_t* r, uint32_t addr) {
    asm volatile("ldmatrix.sync.aligned.m8n8.x4.shared.b16 {%0,%1,%2,%3}, [%4];"
                 : "=r"(r[0]), "=r"(r[1]), "=r"(r[2]), "=r"(r[3]) : "r"(addr));
}
__device__ __forceinline__ void mma_fp16(float* d, const uint32_t* a,
                                         const uint32_t* b) {
    asm volatile(
        "mma.sync.aligned.m16n8k16.row.col.f32.f16.f16.f32 "
        "{%0,%1,%2,%3}, {%4,%5,%6,%7}, {%8,%9}, {%0,%1,%2,%3};"
        : "+f"(d[0]), "+f"(d[1]), "+f"(d[2]), "+f"(d[3])
        : "r"(a[0]), "r"(a[1]), "r"(a[2]), "r"(a[3]), "r"(b[0]), "r"(b[1]));
}

// ---------------------------------------------------------------------------
// Fused fp32 -> fp16 convert: x then Wk, Wr, Wo
// ---------------------------------------------------------------------------
#define NX4 ((Mc * Kc) / 4)       // 4194304
#define NW4 ((Cc * Kc) / 4)       // 262144
#define NCVT (NX4 + 3 * NW4)      // 4980736 (= 19456 * 256)

__global__ void cvt_all(const float* __restrict__ x,
                        const float* __restrict__ Wk,
                        const float* __restrict__ Wr,
                        const float* __restrict__ Wo,
                        __half* __restrict__ xh,
                        __half* __restrict__ wkh,
                        __half* __restrict__ wrh,
                        __half* __restrict__ woh)
{
    int i = blockIdx.x * blockDim.x + threadIdx.x;
    if (i >= NCVT) return;
    const float* src;
    __half* dst;
    int j = i;
    if (j < NX4)              { src = x;  dst = xh;  }
    else if ((j -= NX4) < NW4){ src = Wk; dst = wkh; }
    else if ((j -= NW4) < NW4){ src = Wr; dst = wrh; }
    else                      { j -= NW4; src = Wo; dst = woh; }
    float4 v = reinterpret_cast<const float4*>(src)[j];
    reinterpret_cast<__half2*>(dst)[2 * j]     = __floats2half2_rn(v.x, v.y);
    reinterpret_cast<__half2*>(dst)[2 * j + 1] = __floats2half2_rn(v.z, v.w);
}

// ---------------------------------------------------------------------------
// HMMA fp16 NT GEMM (R8 structure — measured best): C = A * B^T.
// CTA tile 128(M) x 256(N), K-chunk 64 (128B swizzled rows), 8 warps in a
// 2(m) x 4(n) grid -> warp tile 64x64. 4-stage cp.async pipeline, issue
// after compute, two __syncthreads per chunk.
// ---------------------------------------------------------------------------
#define BK 64
#define B_OFF   16384               // A tile 128*128B
#define STAGE_B 49152               // A(16KB) + B(32KB)
#define NSTAGE  4
#define GEMM_SMEM (NSTAGE * STAGE_B)   // 196608
#define NCHUNK (Kc / BK)            // 16

__global__ __launch_bounds__(256, 1)
void gemm_hmma(const __half* __restrict__ A,
               const __half* __restrict__ B0,
               void* __restrict__ C0,
               const __half* __restrict__ B1,
               void* __restrict__ C1,
               int half_out)
{
    extern __shared__ char smem_raw[];
    const uint32_t sbase = smem_u32(smem_raw);

    const int tid  = threadIdx.x;
    const int wid  = tid >> 5;
    const int lane = tid & 31;

    const __half* B = blockIdx.z ? B1 : B0;
    void* Cmat      = blockIdx.z ? C1 : C0;

    const int m0 = blockIdx.y * 128;
    const int n0 = blockIdx.x * 256;

    const __half* Ap = A + (size_t)m0 * Kc;
    const __half* Bp = B + (size_t)n0 * Kc;

    // ---- cp.async segment maps ---------------------------------------------
    uint32_t sdstA[4], goffA[4];
#pragma unroll
    for (int i = 0; i < 4; i++) {
        const int sid = i * 256 + tid;        // 0..1023
        const int row = sid >> 3;             // 0..127
        const int s   = sid & 7;
        sdstA[i] = row * 128 + ((s ^ (row & 7)) << 4);
        goffA[i] = row * Kc + s * 8;
    }
    uint32_t sdstB[8], goffB[8];
#pragma unroll
    for (int j = 0; j < 8; j++) {
        const int sid = j * 256 + tid;        // 0..2047
        const int row = sid >> 3;             // 0..255
        const int s   = sid & 7;
        sdstB[j] = B_OFF + row * 128 + ((s ^ (row & 7)) << 4);
        goffB[j] = row * Kc + s * 8;
    }

    // ---- warp tiling -------------------------------------------------------
    const int wm = (wid & 1) * 64;
    const int wn = (wid >> 1) * 64;

    float acc[4][8][4];
#pragma unroll
    for (int mi = 0; mi < 4; mi++)
#pragma unroll
        for (int ni = 0; ni < 8; ni++)
#pragma unroll
            for (int j = 0; j < 4; j++) acc[mi][ni][j] = 0.f;

    const int a_row = wm + (lane & 15);
    const int a_ks  = lane >> 4;
    const int b_row = wn + (lane & 7) + ((lane >> 4) << 3);
    const int b_ks  = (lane >> 3) & 1;

#define ISSUE_CHUNK(chunk) do {                                                \
    const uint32_t _buf = sbase + ((chunk) & (NSTAGE - 1)) * STAGE_B;          \
    const int _ko = (chunk) * BK;                                              \
    _Pragma("unroll")                                                          \
    for (int i = 0; i < 4; i++)                                                \
        cp_async16(_buf + sdstA[i], Ap + goffA[i] + _ko);                      \
    _Pragma("unroll")                                                          \
    for (int j = 0; j < 8; j++)                                                \
        cp_async16(_buf + sdstB[j], Bp + goffB[j] + _ko);                      \
    cp_commit();                                                               \
} while (0)

    ISSUE_CHUNK(0);
    ISSUE_CHUNK(1);
    ISSUE_CHUNK(2);

    for (int c = 0; c < NCHUNK; ++c) {
        if (c <= NCHUNK - 3)      cp_wait2();
        else if (c == NCHUNK - 2) cp_wait1();
        else                      cp_wait0();
        __syncthreads();

        const uint32_t buf = sbase + (c & (NSTAGE - 1)) * STAGE_B;
#pragma unroll
        for (int ks = 0; ks < 4; ks++) {
            uint32_t af[4][4];
#pragma unroll
            for (int mi = 0; mi < 4; mi++) {
                const int row = a_row + mi * 16;
                const int sg  = (ks * 2 + a_ks) ^ (row & 7);
                ldm_x4(af[mi], buf + row * 128 + (sg << 4));
            }
#pragma unroll
            for (int ni = 0; ni < 4; ni++) {
                const int row = b_row + ni * 16;
                const int sg  = (ks * 2 + b_ks) ^ (row & 7);
                uint32_t bh[4];
                ldm_x4(bh, buf + B_OFF + row * 128 + (sg << 4));
#pragma unroll
                for (int mi = 0; mi < 4; mi++) {
                    mma_fp16(acc[mi][2 * ni],     af[mi], bh);
                    mma_fp16(acc[mi][2 * ni + 1], af[mi], bh + 2);
                }
            }
        }
        __syncthreads();
        if (c + 3 < NCHUNK) {
            ISSUE_CHUNK(c + 3);
        }
    }
#undef ISSUE_CHUNK

    // ---- epilogue ----------------------------------------------------------
    const int er = lane >> 2;
    const int ec = (lane & 3) * 2;
    if (half_out) {
        __half* C = (__half*)Cmat;
#pragma unroll
        for (int mi = 0; mi < 4; mi++) {
            const int mb = m0 + wm + mi * 16;
#pragma unroll
            for (int ni = 0; ni < 8; ni++) {
                const int nb = n0 + wn + ni * 8;
                *reinterpret_cast<__half2*>(C + (size_t)(mb + er) * Cc + nb + ec) =
                    __floats2half2_rn(acc[mi][ni][0], acc[mi][ni][1]);
                *reinterpret_cast<__half2*>(C + (size_t)(mb + 8 + er) * Cc + nb + ec) =
                    __floats2half2_rn(acc[mi][ni][2], acc[mi][ni][3]);
            }
        }
    } else {
        float* C = (float*)Cmat;
#pragma unroll
        for (int mi = 0; mi < 4; mi++) {
            const int mb = m0 + wm + mi * 16;
#pragma unroll
            for (int ni = 0; ni < 8; ni++) {
                const int nb = n0 + wn + ni * 8;
                float2 v0 = make_float2(acc[mi][ni][0], acc[mi][ni][1]);
                float2 v1 = make_float2(acc[mi][ni][2], acc[mi][ni][3]);
                *reinterpret_cast<float2*>(C + (size_t)(mb + er) * Cc + nb + ec) = v0;
                *reinterpret_cast<float2*>(C + (size_t)(mb + 8 + er) * Cc + nb + ec) = v1;
            }
        }
    }
}

// ---------------------------------------------------------------------------
// WKV pass 1 (half2): per-segment partial (num, den) for 2 channels/thread.
//   local = sum_i ew^(L-1-i) * e^{k_i} * [v_i, 1]
// idx = seg*HL + bc2; writes one float4 (n0, n1, d0, d1).
// ---------------------------------------------------------------------------
__global__ void wkv_pass1(const __half2* __restrict__ kbuf,
                          const __half2* __restrict__ rbuf,
                          const float* __restrict__ td,
                          float4* __restrict__ pc)
{
    const int idx = blockIdx.x * blockDim.x + threadIdx.x;
    if (idx >= NSEG * HL) return;
    const int c2  = idx & (Cc / 2 - 1);
    const int b   = (idx >> 9) & (Bc - 1);
    const int seg = idx >> 13;

    const float ew0 = __expf(-__expf(td[2 * c2]));
    const float ew1 = __expf(-__expf(td[2 * c2 + 1]));

    const size_t base = ((size_t)b * Tc + (size_t)seg * SEGL) * (Cc / 2) + c2;
    const __half2* kp = kbuf + base;
    const __half2* rp = rbuf + base;

    float n0 = 0.f, d0 = 0.f, n1 = 0.f, d1 = 0.f;
    for (int t = 0; t < SEGL; t += 8) {
        float2 kt[8], rt[8];
#pragma unroll
        for (int j = 0; j < 8; j++) {                 // MLP = 16
            kt[j] = __half22float2(kp[(size_t)(t + j) * (Cc / 2)]);
            rt[j] = __half22float2(rp[(size_t)(t + j) * (Cc / 2)]);
        }
#pragma unroll
        for (int j = 0; j < 8; j++) {
            const float e0 = __expf(kt[j].x);
            const float e1 = __expf(kt[j].y);
            n0 = fmaf(ew0, n0, e0 * rt[j].x);
            d0 = fmaf(ew0, d0, e0);
            n1 = fmaf(ew1, n1, e1 * rt[j].y);
            d1 = fmaf(ew1, d1, e1);
        }
    }
    pc[idx] = make_float4(n0, n1, d0, d1);
}

// ---------------------------------------------------------------------------
// WKV pass 2 (coalesced mapping): prefix-combine carries from gmem
// (float4, warp-coalesced), rescan segment. Output fused as one fast divide:
//   o = (euk*r + num) / ((den + euk) * (1 + e^-r))
// -> 3 MUFU ops per element (e^k, e^-r, rcp), low register count.
// ---------------------------------------------------------------------------
__global__ void wkv_pass2(const __half2* __restrict__ kbuf,
                          const __half2* __restrict__ rbuf,
                          const float* __restrict__ td,
                          const float* __restrict__ tf,
                          const float4* __restrict__ pc,
                          __half2* __restrict__ obuf)
{
    const int idx = blockIdx.x * blockDim.x + threadIdx.x;
    if (idx >= NSEG * HL) return;
    const int c2  = idx & (Cc / 2 - 1);
    const int b   = (idx >> 9) & (Bc - 1);
    const int bc2 = idx & (HL - 1);
    const int seg = idx >> 13;

    const float etd0 = __expf(td[2 * c2]);
    const float etd1 = __expf(td[2 * c2 + 1]);
    const float ew0  = __expf(-etd0);
    const float ew1  = __expf(-etd1);
    const float ewL0 = __expf(-etd0 * (float)SEGL);
    const float ewL1 = __expf(-etd1 * (float)SEGL);
    const float eu0  = __expf(tf[2 * c2]);
    const float eu1  = __expf(tf[2 * c2 + 1]);

    // carry = combine of segments 0..seg-1 (coalesced 16B float4 loads)
    float n0 = 0.f, d0 = 0.f, n1 = 0.f, d1 = 0.f;
    for (int s = 0; s < seg; s++) {
        const float4 p = pc[s * HL + bc2];
        n0 = fmaf(ewL0, n0, p.x);
        n1 = fmaf(ewL1, n1, p.y);
        d0 = fmaf(ewL0, d0, p.z);
        d1 = fmaf(ewL1, d1, p.w);
    }

    const size_t base = ((size_t)b * Tc + (size_t)seg * SEGL) * (Cc / 2) + c2;
    const __half2* kp = kbuf + base;
    const __half2* rp = rbuf + base;
    __half2*       op = obuf + base;

    for (int t = 0; t < SEGL; t += 8) {
        float2 kt[8], rt[8];
#pragma unroll
        for (int j = 0; j < 8; j++) {
            kt[j] = __half22float2(kp[(size_t)(t + j) * (Cc / 2)]);
            rt[j] = __half22float2(rp[(size_t)(t + j) * (Cc / 2)]);
        }
#pragma unroll
        for (int j = 0; j < 8; j++) {
            const float e0  = __expf(kt[j].x);              // MUFU 1
            const float e1  = __expf(kt[j].y);
            const float em0 = __expf(-rt[j].x);             // MUFU 2
            const float em1 = __expf(-rt[j].y);
            const float eu_k0 = eu0 * e0;
            const float eu_k1 = eu1 * e1;
            const float num0 = fmaf(eu_k0, rt[j].x, n0);
            const float num1 = fmaf(eu_k1, rt[j].y, n1);
            const float den0 = (d0 + eu_k0) * (1.f + em0);
            const float den1 = (d1 + eu_k1) * (1.f + em1);
            const float o0 = __fdividef(num0, den0);        // MUFU 3 (rcp)
            const float o1 = __fdividef(num1, den1);
            n0 = fmaf(ew0, n0, e0 * rt[j].x);
            d0 = fmaf(ew0, d0, e0);
            n1 = fmaf(ew1, n1, e1 * rt[j].y);
            d1 = fmaf(ew1, d1, e1);
            op[(size_t)(t + j) * (Cc / 2)] = __floats2half2_rn(o0, o1);
        }
    }
}

// ---------------------------------------------------------------------------
// Launch sequence (graph-capturable; default stream)
// ---------------------------------------------------------------------------
extern "C" void kernel_launch(void* const* d_in, const int* in_sizes, int n_in,
                              void* d_out, int out_size)
{
    const float* x  = (const float*)d_in[0];
    const float* Wk = (const float*)d_in[1];
    const float* Wr = (const float*)d_in[2];
    const float* Wo = (const float*)d_in[3];
    const float* td = (const float*)d_in[4];
    const float* tf = (const float*)d_in[5];
    float* out = (float*)d_out;

    __half *xh, *of, *wkh, *wrh, *woh, *pk, *pr;
    float4* pc;
    cudaGetSymbolAddress((void**)&xh,  g_xh);
    cudaGetSymbolAddress((void**)&of,  g_of);
    cudaGetSymbolAddress((void**)&pk,  g_k);
    cudaGetSymbolAddress((void**)&pr,  g_r);
    cudaGetSymbolAddress((void**)&wkh, g_wkh);
    cudaGetSymbolAddress((void**)&wrh, g_wrh);
    cudaGetSymbolAddress((void**)&woh, g_woh);
    cudaGetSymbolAddress((void**)&pc,  g_pc);

    cudaFuncSetAttribute(gemm_hmma, cudaFuncAttributeMaxDynamicSharedMemorySize,
                         GEMM_SMEM);

    // fused fp32 -> fp16 conversions (x + all three weights)
    cvt_all<<<NCVT / 256, 256>>>(x, Wk, Wr, Wo, xh, wkh, wrh, woh);

    // z=0: k = x*Wk^T ; z=1: r = x*Wr^T ; both -> fp16
    dim3 grid_kr(Cc / 256, Mc / 128, 2);
    gemm_hmma<<<grid_kr, 256, GEMM_SMEM>>>(xh, wkh, pk, wrh, pr, 1);

    // segment-parallel wkv
    wkv_pass1<<<(NSEG * HL) / 256, 256>>>((const __half2*)pk,
                                          (const __half2*)pr, td, pc);
    wkv_pass2<<<(NSEG * HL) / 256, 256>>>((const __half2*)pk,
                                          (const __half2*)pr, td, tf, pc,
                                          (__half2*)of);

    // out = o * Wo^T, fp32 output
    dim3 grid_o(Cc / 256, Mc / 128, 1);
    gemm_hmma<<<grid_o, 256, GEMM_SMEM>>>(of, woh, out, woh, out, 0);
}

// round 15
// speedup vs baseline: 1.1025x; 1.0944x over previous
#include <cuda_runtime.h>
#include <cuda_fp16.h>
#include <cstdint>
#include <cstddef>

// Problem shape (fixed)
#define Bc 16
#define Tc 1024
#define Cc 1024
#define Kc 1024
#define Mc (Bc * Tc)   // 16384
#define NSEG 32
#define SEGL (Tc / NSEG)   // 32
#define LANES (Bc * Cc)    // 16384
#define HL (LANES / 2)     // 8192 half2 lanes

// ---------------------------------------------------------------------------
// Scratch (__device__ globals; no cudaMalloc allowed)
// ---------------------------------------------------------------------------
__device__ __half  g_xh [(size_t)Mc * Kc];    // x as fp16
__device__ __half  g_of [(size_t)Mc * Kc];    // gated wkv output as fp16
__device__ __half  g_k  [(size_t)Mc * Cc];    // k as fp16
__device__ __half  g_r  [(size_t)Mc * Cc];    // r as fp16
__device__ __half  g_wkh[Cc * Kc];            // Wk fp16
__device__ __half  g_wrh[Cc * Kc];            // Wr fp16
__device__ __half  g_woh[Cc * Kc];            // Wo fp16
__device__ float4  g_pc [NSEG * HL];          // per-segment partials (n0,n1,d0,d1)

// ---------------------------------------------------------------------------
// Base-ISA PTX helpers (compile for plain .target sm_103)
// ---------------------------------------------------------------------------
__device__ __forceinline__ uint32_t smem_u32(const void* p) {
    uint32_t a;
    asm("{ .reg .u64 t; cvta.to.shared.u64 t, %1; cvt.u32.u64 %0, t; }"
        : "=r"(a) : "l"(p));
    return a;
}
__device__ __forceinline__ void cp_async16(uint32_t dst, const void* src) {
    asm volatile("cp.async.cg.shared.global [%0], [%1], 16;"
                 :: "r"(dst), "l"(src));
}
__device__ __forceinline__ void cp_commit() {
    asm volatile("cp.async.commit_group;");
}
__device__ __forceinline__ void cp_wait2() {
    asm volatile("cp.async.wait_group 2;" ::: "memory");
}
__device__ __forceinline__ void cp_wait1() {
    asm volatile("cp.async.wait_group 1;" ::: "memory");
}
__device__ __forceinline__ void cp_wait0() {
    asm volatile("cp.async.wait_group 0;" ::: "memory");
}
__device__ __forceinline__ void ldm_x4(uint32_t* r, uint32_t addr) {
    asm volatile("ldmatrix.sync.aligned.m8n8.x4.shared.b16 {%0,%1,%2,%3}, [%4];"
                 : "=r"(r[0]), "=r"(r[1]), "=r"(r[2]), "=r"(r[3]) : "r"(addr));
}
__device__ __forceinline__ void mma_fp16(float* d, const uint32_t* a,
                                         const uint32_t* b) {
    asm volatile(
        "mma.sync.aligned.m16n8k16.row.col.f32.f16.f16.f32 "
        "{%0,%1,%2,%3}, {%4,%5,%6,%7}, {%8,%9}, {%0,%1,%2,%3};"
        : "+f"(d[0]), "+f"(d[1]), "+f"(d[2]), "+f"(d[3])
        : "r"(a[0]), "r"(a[1]), "r"(a[2]), "r"(a[3]), "r"(b[0]), "r"(b[1]));
}

// ---------------------------------------------------------------------------
// Fused fp32 -> fp16 convert: x then Wk, Wr, Wo
// ---------------------------------------------------------------------------
#define NX4 ((Mc * Kc) / 4)       // 4194304
#define NW4 ((Cc * Kc) / 4)       // 262144
#define NCVT (NX4 + 3 * NW4)      // 4980736 (= 19456 * 256)

__global__ void cvt_all(const float* __restrict__ x,
                        const float* __restrict__ Wk,
                        const float* __restrict__ Wr,
                        const float* __restrict__ Wo,
                        __half* __restrict__ xh,
                        __half* __restrict__ wkh,
                        __half* __restrict__ wrh,
                        __half* __restrict__ woh)
{
    int i = blockIdx.x * blockDim.x + threadIdx.x;
    if (i >= NCVT) return;
    const float* src;
    __half* dst;
    int j = i;
    if (j < NX4)              { src = x;  dst = xh;  }
    else if ((j -= NX4) < NW4){ src = Wk; dst = wkh; }
    else if ((j -= NW4) < NW4){ src = Wr; dst = wrh; }
    else                      { j -= NW4; src = Wo; dst = woh; }
    float4 v = reinterpret_cast<const float4*>(src)[j];
    reinterpret_cast<__half2*>(dst)[2 * j]     = __floats2half2_rn(v.x, v.y);
    reinterpret_cast<__half2*>(dst)[2 * j + 1] = __floats2half2_rn(v.z, v.w);
}

// ---------------------------------------------------------------------------
// HMMA fp16 NT GEMM, 2-CTA/SM variant: C[M,1024] = A[M,K] * B[N,K]^T.
// CTA tile 128(M) x 128(N), K-chunk 64 (128B swizzled rows), 8 warps in a
// 2(m) x 4(n) grid -> warp tile 64x32. 3-stage cp.async pipeline (96KB SMEM)
// so TWO CTAs co-reside per SM: one CTA's MMAs fill the other's sync/copy
// stalls. Same per-output math/summation order as before (bit-identical).
// ---------------------------------------------------------------------------
#define BK 64
#define B_OFF   16384               // A tile 128*128B
#define STAGE_B 32768               // A(16KB) + B(16KB)
#define NSTAGE  3
#define GEMM_SMEM (NSTAGE * STAGE_B)   // 98304
#define NCHUNK (Kc / BK)            // 16

__global__ __launch_bounds__(256, 2)
void gemm_hmma(const __half* __restrict__ A,
               const __half* __restrict__ B0,
               void* __restrict__ C0,
               const __half* __restrict__ B1,
               void* __restrict__ C1,
               int half_out)
{
    extern __shared__ char smem_raw[];
    const uint32_t sbase = smem_u32(smem_raw);

    const int tid  = threadIdx.x;
    const int wid  = tid >> 5;
    const int lane = tid & 31;

    const __half* B = blockIdx.z ? B1 : B0;
    void* Cmat      = blockIdx.z ? C1 : C0;

    const int m0 = blockIdx.y * 128;
    const int n0 = blockIdx.x * 128;

    const __half* Ap = A + (size_t)m0 * Kc;
    const __half* Bp = B + (size_t)n0 * Kc;

    // ---- cp.async segment maps (A: 128 rows, B: 128 rows; 8 segs/row) -----
    uint32_t sdstA[4], goffA[4];
#pragma unroll
    for (int i = 0; i < 4; i++) {
        const int sid = i * 256 + tid;        // 0..1023
        const int row = sid >> 3;             // 0..127
        const int s   = sid & 7;
        sdstA[i] = row * 128 + ((s ^ (row & 7)) << 4);
        goffA[i] = row * Kc + s * 8;
    }
    uint32_t sdstB[4], goffB[4];
#pragma unroll
    for (int j = 0; j < 4; j++) {
        const int sid = j * 256 + tid;        // 0..1023
        const int row = sid >> 3;             // 0..127
        const int s   = sid & 7;
        sdstB[j] = B_OFF + row * 128 + ((s ^ (row & 7)) << 4);
        goffB[j] = row * Kc + s * 8;
    }

    // ---- warp tiling: 2(m) x 4(n) -> warp tile 64x32 -----------------------
    const int wm = (wid & 1) * 64;
    const int wn = (wid >> 1) * 32;

    float acc[4][4][4];
#pragma unroll
    for (int mi = 0; mi < 4; mi++)
#pragma unroll
        for (int ni = 0; ni < 4; ni++)
#pragma unroll
            for (int j = 0; j < 4; j++) acc[mi][ni][j] = 0.f;

    const int a_row = wm + (lane & 15);
    const int a_ks  = lane >> 4;
    const int b_row = wn + (lane & 7) + ((lane >> 4) << 3);
    const int b_ks  = (lane >> 3) & 1;

#define ISSUE_CHUNK(chunk) do {                                                \
    const uint32_t _buf = sbase + ((chunk) % NSTAGE) * STAGE_B;                \
    const int _ko = (chunk) * BK;                                              \
    _Pragma("unroll")                                                          \
    for (int i = 0; i < 4; i++)                                                \
        cp_async16(_buf + sdstA[i], Ap + goffA[i] + _ko);                      \
    _Pragma("unroll")                                                          \
    for (int j = 0; j < 4; j++)                                                \
        cp_async16(_buf + sdstB[j], Bp + goffB[j] + _ko);                      \
    cp_commit();                                                               \
} while (0)

    ISSUE_CHUNK(0);
    ISSUE_CHUNK(1);
    ISSUE_CHUNK(2);

    for (int c = 0; c < NCHUNK; ++c) {
        if (c <= NCHUNK - 3)      cp_wait2();
        else if (c == NCHUNK - 2) cp_wait1();
        else                      cp_wait0();
        __syncthreads();

        const uint32_t buf = sbase + (c % NSTAGE) * STAGE_B;
#pragma unroll
        for (int ks = 0; ks < 4; ks++) {
            uint32_t af[4][4];
#pragma unroll
            for (int mi = 0; mi < 4; mi++) {
                const int row = a_row + mi * 16;
                const int sg  = (ks * 2 + a_ks) ^ (row & 7);
                ldm_x4(af[mi], buf + row * 128 + (sg << 4));
            }
#pragma unroll
            for (int ni = 0; ni < 2; ni++) {
                const int row = b_row + ni * 16;
                const int sg  = (ks * 2 + b_ks) ^ (row & 7);
                uint32_t bh[4];
                ldm_x4(bh, buf + B_OFF + row * 128 + (sg << 4));
#pragma unroll
                for (int mi = 0; mi < 4; mi++) {
                    mma_fp16(acc[mi][2 * ni],     af[mi], bh);
                    mma_fp16(acc[mi][2 * ni + 1], af[mi], bh + 2);
                }
            }
        }
        __syncthreads();
        if (c + 3 < NCHUNK) {
            ISSUE_CHUNK(c + 3);
        }
    }
#undef ISSUE_CHUNK

    // ---- epilogue ----------------------------------------------------------
    const int er = lane >> 2;
    const int ec = (lane & 3) * 2;
    if (half_out) {
        __half* C = (__half*)Cmat;
#pragma unroll
        for (int mi = 0; mi < 4; mi++) {
            const int mb = m0 + wm + mi * 16;
#pragma unroll
            for (int ni = 0; ni < 4; ni++) {
                const int nb = n0 + wn + ni * 8;
                *reinterpret_cast<__half2*>(C + (size_t)(mb + er) * Cc + nb + ec) =
                    __floats2half2_rn(acc[mi][ni][0], acc[mi][ni][1]);
                *reinterpret_cast<__half2*>(C + (size_t)(mb + 8 + er) * Cc + nb + ec) =
                    __floats2half2_rn(acc[mi][ni][2], acc[mi][ni][3]);
            }
        }
    } else {
        float* C = (float*)Cmat;
#pragma unroll
        for (int mi = 0; mi < 4; mi++) {
            const int mb = m0 + wm + mi * 16;
#pragma unroll
            for (int ni = 0; ni < 4; ni++) {
                const int nb = n0 + wn + ni * 8;
                float2 v0 = make_float2(acc[mi][ni][0], acc[mi][ni][1]);
                float2 v1 = make_float2(acc[mi][ni][2], acc[mi][ni][3]);
                *reinterpret_cast<float2*>(C + (size_t)(mb + er) * Cc + nb + ec) = v0;
                *reinterpret_cast<float2*>(C + (size_t)(mb + 8 + er) * Cc + nb + ec) = v1;
            }
        }
    }
}

// ---------------------------------------------------------------------------
// WKV pass 1 (half2): per-segment partial (num, den) for 2 channels/thread.
// ---------------------------------------------------------------------------
__global__ void wkv_pass1(const __half2* __restrict__ kbuf,
                          const __half2* __restrict__ rbuf,
                          const float* __restrict__ td,
                          float4* __restrict__ pc)
{
    const int idx = blockIdx.x * blockDim.x + threadIdx.x;
    if (idx >= NSEG * HL) return;
    const int c2  = idx & (Cc / 2 - 1);
    const int b   = (idx >> 9) & (Bc - 1);
    const int seg = idx >> 13;

    const float ew0 = __expf(-__expf(td[2 * c2]));
    const float ew1 = __expf(-__expf(td[2 * c2 + 1]));

    const size_t base = ((size_t)b * Tc + (size_t)seg * SEGL) * (Cc / 2) + c2;
    const __half2* kp = kbuf + base;
    const __half2* rp = rbuf + base;

    float n0 = 0.f, d0 = 0.f, n1 = 0.f, d1 = 0.f;
    for (int t = 0; t < SEGL; t += 8) {
        float2 kt[8], rt[8];
#pragma unroll
        for (int j = 0; j < 8; j++) {                 // MLP = 16
            kt[j] = __half22float2(kp[(size_t)(t + j) * (Cc / 2)]);
            rt[j] = __half22float2(rp[(size_t)(t + j) * (Cc / 2)]);
        }
#pragma unroll
        for (int j = 0; j < 8; j++) {
            const float e0 = __expf(kt[j].x);
            const float e1 = __expf(kt[j].y);
            n0 = fmaf(ew0, n0, e0 * rt[j].x);
            d0 = fmaf(ew0, d0, e0);
            n1 = fmaf(ew1, n1, e1 * rt[j].y);
            d1 = fmaf(ew1, d1, e1);
        }
    }
    pc[idx] = make_float4(n0, n1, d0, d1);
}

// ---------------------------------------------------------------------------
// WKV pass 2: prefix-combine carries (coalesced float4), rescan segment.
//   o = (euk*r + num) / ((den + euk) * (1 + e^-r))   [one fast divide]
// ---------------------------------------------------------------------------
__global__ void wkv_pass2(const __half2* __restrict__ kbuf,
                          const __half2* __restrict__ rbuf,
                          const float* __restrict__ td,
                          const float* __restrict__ tf,
                          const float4* __restrict__ pc,
                          __half2* __restrict__ obuf)
{
    const int idx = blockIdx.x * blockDim.x + threadIdx.x;
    if (idx >= NSEG * HL) return;
    const int c2  = idx & (Cc / 2 - 1);
    const int b   = (idx >> 9) & (Bc - 1);
    const int bc2 = idx & (HL - 1);
    const int seg = idx >> 13;

    const float etd0 = __expf(td[2 * c2]);
    const float etd1 = __expf(td[2 * c2 + 1]);
    const float ew0  = __expf(-etd0);
    const float ew1  = __expf(-etd1);
    const float ewL0 = __expf(-etd0 * (float)SEGL);
    const float ewL1 = __expf(-etd1 * (float)SEGL);
    const float eu0  = __expf(tf[2 * c2]);
    const float eu1  = __expf(tf[2 * c2 + 1]);

    float n0 = 0.f, d0 = 0.f, n1 = 0.f, d1 = 0.f;
    for (int s = 0; s < seg; s++) {
        const float4 p = pc[s * HL + bc2];
        n0 = fmaf(ewL0, n0, p.x);
        n1 = fmaf(ewL1, n1, p.y);
        d0 = fmaf(ewL0, d0, p.z);
        d1 = fmaf(ewL1, d1, p.w);
    }

    const size_t base = ((size_t)b * Tc + (size_t)seg * SEGL) * (Cc / 2) + c2;
    const __half2* kp = kbuf + base;
    const __half2* rp = rbuf + base;
    __half2*       op = obuf + base;

    for (int t = 0; t < SEGL; t += 8) {
        float2 kt[8], rt[8];
#pragma unroll
        for (int j = 0; j < 8; j++) {
            kt[j] = __half22float2(kp[(size_t)(t + j) * (Cc / 2)]);
            rt[j] = __half22float2(rp[(size_t)(t + j) * (Cc / 2)]);
        }
#pragma unroll
        for (int j = 0; j < 8; j++) {
            const float e0  = __expf(kt[j].x);
            const float e1  = __expf(kt[j].y);
            const float em0 = __expf(-rt[j].x);
            const float em1 = __expf(-rt[j].y);
            const float eu_k0 = eu0 * e0;
            const float eu_k1 = eu1 * e1;
            const float num0 = fmaf(eu_k0, rt[j].x, n0);
            const float num1 = fmaf(eu_k1, rt[j].y, n1);
            const float den0 = (d0 + eu_k0) * (1.f + em0);
            const float den1 = (d1 + eu_k1) * (1.f + em1);
            const float o0 = __fdividef(num0, den0);
            const float o1 = __fdividef(num1, den1);
            n0 = fmaf(ew0, n0, e0 * rt[j].x);
            d0 = fmaf(ew0, d0, e0);
            n1 = fmaf(ew1, n1, e1 * rt[j].y);
            d1 = fmaf(ew1, d1, e1);
            op[(size_t)(t + j) * (Cc / 2)] = __floats2half2_rn(o0, o1);
        }
    }
}

// ---------------------------------------------------------------------------
// Launch sequence (graph-capturable; default stream)
// ---------------------------------------------------------------------------
extern "C" void kernel_launch(void* const* d_in, const int* in_sizes, int n_in,
                              void* d_out, int out_size)
{
    const float* x  = (const float*)d_in[0];
    const float* Wk = (const float*)d_in[1];
    const float* Wr = (const float*)d_in[2];
    const float* Wo = (const float*)d_in[3];
    const float* td = (const float*)d_in[4];
    const float* tf = (const float*)d_in[5];
    float* out = (float*)d_out;

    __half *xh, *of, *wkh, *wrh, *woh, *pk, *pr;
    float4* pc;
    cudaGetSymbolAddress((void**)&xh,  g_xh);
    cudaGetSymbolAddress((void**)&of,  g_of);
    cudaGetSymbolAddress((void**)&pk,  g_k);
    cudaGetSymbolAddress((void**)&pr,  g_r);
    cudaGetSymbolAddress((void**)&wkh, g_wkh);
    cudaGetSymbolAddress((void**)&wrh, g_wrh);
    cudaGetSymbolAddress((void**)&woh, g_woh);
    cudaGetSymbolAddress((void**)&pc,  g_pc);

    cudaFuncSetAttribute(gemm_hmma, cudaFuncAttributeMaxDynamicSharedMemorySize,
                         GEMM_SMEM);

    // fused fp32 -> fp16 conversions (x + all three weights)
    cvt_all<<<NCVT / 256, 256>>>(x, Wk, Wr, Wo, xh, wkh, wrh, woh);

    // z=0: k = x*Wk^T ; z=1: r = x*Wr^T ; both -> fp16
    dim3 grid_kr(Cc / 128, Mc / 128, 2);
    gemm_hmma<<<grid_kr, 256, GEMM_SMEM>>>(xh, wkh, pk, wrh, pr, 1);

    // segment-parallel wkv
    wkv_pass1<<<(NSEG * HL) / 256, 256>>>((const __half2*)pk,
                                          (const __half2*)pr, td, pc);
    wkv_pass2<<<(NSEG * HL) / 256, 256>>>((const __half2*)pk,
                                          (const __half2*)pr, td, tf, pc,
                                          (__half2*)of);

    // out = o * Wo^T, fp32 output
    dim3 grid_o(Cc / 128, Mc / 128, 1);
    gemm_hmma<<<grid_o, 256, GEMM_SMEM>>>(of, woh, out, woh, out, 0);
}